// round 1
// baseline (speedup 1.0000x reference)
#include <cuda_runtime.h>
#include <math.h>

#define BB 4
#define LL 1024
#define HID 512
#define HEADS 8
#define HD 64

// Scratch (device globals: allocation-free)
__device__ float g_q[BB*LL*HID];
__device__ float g_k[BB*LL*HID];
__device__ float g_v[BB*LL*HID];
__device__ float g_ctx[BB*LL*HID];

struct GArgs {
    const float* A[3];
    const float* W[3];
    const float* bias[3];
    float* C[3];
};

// C[m,n] = sum_k A[m,k]*W[n,k] + bias[n]   (NT gemm, both row-major K-contig)
// M=4096, N=512, K=512. 64x64 tile, 16-wide k tiles, 256 threads, 4x4/thread.
__global__ __launch_bounds__(256) void gemm_nt_bias(GArgs args) {
    const int M = BB*LL, N = HID, K = HID;
    (void)M;
    __shared__ float As[64][17];
    __shared__ float Ws[64][17];
    const int z = blockIdx.z;
    const float* __restrict__ A = args.A[z];
    const float* __restrict__ W = args.W[z];
    const float* __restrict__ bias = args.bias[z];
    float* __restrict__ C = args.C[z];

    const int tid = threadIdx.x;
    const int ty = tid >> 4, tx = tid & 15;
    const int m0 = blockIdx.y * 64, n0 = blockIdx.x * 64;
    float acc[4][4] = {};

    for (int k0 = 0; k0 < K; k0 += 16) {
        #pragma unroll
        for (int it = 0; it < 4; ++it) {
            int idx = tid + it * 256;
            int r = idx >> 4, c = idx & 15;
            As[r][c] = A[(size_t)(m0 + r) * K + k0 + c];
            Ws[r][c] = W[(size_t)(n0 + r) * K + k0 + c];
        }
        __syncthreads();
        #pragma unroll
        for (int kk = 0; kk < 16; ++kk) {
            float a[4], b[4];
            #pragma unroll
            for (int i = 0; i < 4; ++i) a[i] = As[ty*4+i][kk];
            #pragma unroll
            for (int j = 0; j < 4; ++j) b[j] = Ws[tx*4+j][kk];
            #pragma unroll
            for (int i = 0; i < 4; ++i)
                #pragma unroll
                for (int j = 0; j < 4; ++j)
                    acc[i][j] = fmaf(a[i], b[j], acc[i][j]);
        }
        __syncthreads();
    }
    #pragma unroll
    for (int i = 0; i < 4; ++i) {
        int m = m0 + ty*4 + i;
        #pragma unroll
        for (int j = 0; j < 4; ++j) {
            int n = n0 + tx*4 + j;
            C[(size_t)m * N + n] = acc[i][j] + bias[n];
        }
    }
}

// Flash-style causal attention with relative-position bias.
// One CTA per (b, h, 64-row q tile). 256 threads, 4x4 register tiles.
// Smem (dynamic, floats): Qs[64*65] Ks[64*65] Vs[64*65] Ps[64*65]
//                         prel[64*6] mrow[64] lrow[64] nearw[64*5]
__global__ __launch_bounds__(256) void attn_kernel(
    const float* __restrict__ gq, const float* __restrict__ gk,
    const float* __restrict__ gv, const float* __restrict__ relk,
    const float* __restrict__ relv, float* __restrict__ gctx)
{
    extern __shared__ float sm[];
    float* Qs   = sm;
    float* Ks   = Qs + 64*65;
    float* Vs   = Ks + 64*65;
    float* Ps   = Vs + 64*65;
    float* prel = Ps + 64*65;     // [64][6] : q-row dot rel_k[j]
    float* mrow = prel + 64*6;    // [64] running max
    float* lrow = mrow + 64;      // [64] running sum
    float* nearw = lrow + 64;     // [64][5] unnormalized attn weight at distance d

    const int tid = threadIdx.x;
    const int ty = tid >> 4, tx = tid & 15;
    const int qt = blockIdx.x;
    const int h  = blockIdx.y;
    const int b  = blockIdx.z;
    const int q0 = qt * 64;
    const size_t base = ((size_t)b * LL) * HID + (size_t)h * HD;

    // Load Q tile
    #pragma unroll
    for (int it = 0; it < 16; ++it) {
        int idx = tid + it * 256;
        int r = idx >> 6, c = idx & 63;
        Qs[r*65 + c] = gq[base + (size_t)(q0 + r) * HID + c];
    }
    if (tid < 64) { mrow[tid] = -1e30f; lrow[tid] = 0.f; }
    for (int idx = tid; idx < 64*5; idx += 256) nearw[idx] = 0.f;
    __syncthreads();

    // prel[r][j] = Q[r] . rel_k[j]   (only rows 0..5 of rel_k are reachable)
    for (int idx = tid; idx < 64*6; idx += 256) {
        int r = idx / 6, j = idx % 6;
        float s = 0.f;
        #pragma unroll
        for (int d = 0; d < HD; ++d) s = fmaf(Qs[r*65 + d], relk[j*HD + d], s);
        prel[r*6 + j] = s;
    }

    float acc[4][4] = {};

    for (int kt = 0; kt <= qt; ++kt) {
        __syncthreads();   // protect Ks/Vs/Ps from previous iteration's PV
        #pragma unroll
        for (int it = 0; it < 16; ++it) {
            int idx = tid + it * 256;
            int r = idx >> 6, c = idx & 63;
            size_t g = base + (size_t)(kt*64 + r) * HID + c;
            Ks[r*65 + c] = gk[g];
            Vs[r*65 + c] = gv[g];
        }
        __syncthreads();

        // S = Q @ K^T  (64x64, register tiled)
        float s[4][4] = {};
        #pragma unroll
        for (int kk = 0; kk < 64; ++kk) {
            float a[4], bb[4];
            #pragma unroll
            for (int i = 0; i < 4; ++i) a[i] = Qs[(ty*4+i)*65 + kk];
            #pragma unroll
            for (int j = 0; j < 4; ++j) bb[j] = Ks[(tx*4+j)*65 + kk];
            #pragma unroll
            for (int i = 0; i < 4; ++i)
                #pragma unroll
                for (int j = 0; j < 4; ++j)
                    s[i][j] = fmaf(a[i], bb[j], s[i][j]);
        }

        const int dq = (qt - kt) * 64;
        const bool neardiag = (dq <= 64);   // only these tiles contain d<5

        // bias + mask + online softmax (per q row; 16 lanes per row group)
        #pragma unroll
        for (int i = 0; i < 4; ++i) {
            const int r = ty*4 + i;
            #pragma unroll
            for (int j = 0; j < 4; ++j) {
                const int c = tx*4 + j;
                const int d = dq + r - c;   // distance q - k
                if (d < 0) {
                    s[i][j] = -1e30f;       // causal mask
                } else {
                    const int id = (d >= 5) ? 0 : (5 - d);
                    s[i][j] = (s[i][j] + prel[r*6 + id]) * 0.125f;  // /sqrt(64)
                }
            }
            float rm = fmaxf(fmaxf(s[i][0], s[i][1]), fmaxf(s[i][2], s[i][3]));
            #pragma unroll
            for (int off = 8; off >= 1; off >>= 1)
                rm = fmaxf(rm, __shfl_xor_sync(0xffffffffu, rm, off));
            const float mold = mrow[r];
            const float mnew = fmaxf(mold, rm);
            const float scale = __expf(mold - mnew);
            float psum = 0.f;
            #pragma unroll
            for (int j = 0; j < 4; ++j) {
                float p = __expf(s[i][j] - mnew);
                s[i][j] = p;                       // keep p for near-weight write
                Ps[r*65 + tx*4 + j] = p;
                psum += p;
            }
            #pragma unroll
            for (int off = 8; off >= 1; off >>= 1)
                psum += __shfl_xor_sync(0xffffffffu, psum, off);
            #pragma unroll
            for (int j = 0; j < 4; ++j) acc[i][j] *= scale;
            if (tx == 0) {
                mrow[r] = mnew;
                lrow[r] = lrow[r] * scale + psum;
                if (neardiag) {
                    #pragma unroll
                    for (int dd = 0; dd < 5; ++dd) nearw[r*5 + dd] *= scale;
                }
            }
        }
        if (neardiag) {
            __syncwarp();   // order tx==0 rescale before owner writes (same warp)
            #pragma unroll
            for (int i = 0; i < 4; ++i) {
                const int r = ty*4 + i;
                #pragma unroll
                for (int j = 0; j < 4; ++j) {
                    const int c = tx*4 + j;
                    const int d = dq + r - c;
                    if (d >= 0 && d < 5) nearw[r*5 + d] = s[i][j];
                }
            }
        }
        __syncthreads();

        // O += P @ V
        #pragma unroll
        for (int kk = 0; kk < 64; ++kk) {
            float a[4], bb[4];
            #pragma unroll
            for (int i = 0; i < 4; ++i) a[i] = Ps[(ty*4+i)*65 + kk];
            #pragma unroll
            for (int j = 0; j < 4; ++j) bb[j] = Vs[kk*65 + tx*4 + j];
            #pragma unroll
            for (int i = 0; i < 4; ++i)
                #pragma unroll
                for (int j = 0; j < 4; ++j)
                    acc[i][j] = fmaf(a[i], bb[j], acc[i][j]);
        }
    }
    __syncthreads();

    // Epilogue: add relative-V term and normalize.
    // w2 = sum_{d=0..4} near[d]*rel_v[5-d] + (l - sum near)*rel_v[0]
    #pragma unroll
    for (int i = 0; i < 4; ++i) {
        const int r = ty*4 + i;
        const float lr = lrow[r];
        const float inv = 1.f / lr;
        const float n0 = nearw[r*5+0], n1 = nearw[r*5+1], n2 = nearw[r*5+2],
                    n3 = nearw[r*5+3], n4 = nearw[r*5+4];
        const float farw = lr - (n0 + n1 + n2 + n3 + n4);
        #pragma unroll
        for (int j = 0; j < 4; ++j) {
            const int c = tx*4 + j;
            float extra = n0 * relv[5*HD + c] + n1 * relv[4*HD + c]
                        + n2 * relv[3*HD + c] + n3 * relv[2*HD + c]
                        + n4 * relv[1*HD + c] + farw * relv[0*HD + c];
            gctx[base + (size_t)(q0 + r) * HID + c] = (acc[i][j] + extra) * inv;
        }
    }
}

extern "C" void kernel_launch(void* const* d_in, const int* in_sizes, int n_in,
                              void* d_out, int out_size) {
    (void)in_sizes; (void)n_in; (void)out_size;
    const float* query = (const float*)d_in[0];
    const float* key   = (const float*)d_in[1];
    const float* value = (const float*)d_in[2];
    const float* Wq = (const float*)d_in[3];
    const float* bq = (const float*)d_in[4];
    const float* Wk = (const float*)d_in[5];
    const float* bk = (const float*)d_in[6];
    const float* Wv = (const float*)d_in[7];
    const float* bv = (const float*)d_in[8];
    const float* Wo = (const float*)d_in[9];
    const float* bo = (const float*)d_in[10];
    const float* relk = (const float*)d_in[11];
    const float* relv = (const float*)d_in[12];

    float *pq, *pk, *pv, *pctx;
    cudaGetSymbolAddress((void**)&pq,  g_q);
    cudaGetSymbolAddress((void**)&pk,  g_k);
    cudaGetSymbolAddress((void**)&pv,  g_v);
    cudaGetSymbolAddress((void**)&pctx, g_ctx);

    // 1) QKV projections (batched in one launch via grid.z)
    GArgs qkv;
    qkv.A[0] = query; qkv.W[0] = Wq; qkv.bias[0] = bq; qkv.C[0] = pq;
    qkv.A[1] = key;   qkv.W[1] = Wk; qkv.bias[1] = bk; qkv.C[1] = pk;
    qkv.A[2] = value; qkv.W[2] = Wv; qkv.bias[2] = bv; qkv.C[2] = pv;
    gemm_nt_bias<<<dim3(HID/64, (BB*LL)/64, 3), 256>>>(qkv);

    // 2) attention
    const int SMEM = (4*64*65 + 64*6 + 64 + 64 + 64*5) * (int)sizeof(float); // 69888
    cudaFuncSetAttribute(attn_kernel,
                         cudaFuncAttributeMaxDynamicSharedMemorySize, SMEM);
    attn_kernel<<<dim3(LL/64, HEADS, BB), 256, SMEM>>>(pq, pk, pv, relk, relv, pctx);

    // 3) output projection
    GArgs og;
    og.A[0] = pctx; og.W[0] = Wo; og.bias[0] = bo; og.C[0] = (float*)d_out;
    og.A[1] = og.A[0]; og.W[1] = og.W[0]; og.bias[1] = og.bias[0]; og.C[1] = og.C[0];
    og.A[2] = og.A[0]; og.W[2] = og.W[0]; og.bias[2] = og.bias[0]; og.C[2] = og.C[0];
    gemm_nt_bias<<<dim3(HID/64, (BB*LL)/64, 1), 256>>>(og);
}

// round 3
// speedup vs baseline: 2.7565x; 2.7565x over previous
#include <cuda_runtime.h>
#include <math.h>
#include <stdint.h>

#define BB 4
#define LL 1024
#define HID 512
#define HEADS 8
#define HD 64

// Scratch (device globals: allocation-free)
__device__ float g_q[BB*LL*HID];
__device__ float g_k[BB*LL*HID];
__device__ float g_v[BB*LL*HID];
__device__ float g_ctx[BB*LL*HID];

struct GArgs {
    const float* A[3];
    const float* W[3];
    const float* bias[3];
    float* C[3];
};

// tf32 round (rna) -> 32-bit pattern in a b32 register
__device__ __forceinline__ uint32_t cvt_tf32(float x) {
    uint32_t r;
    asm("cvt.rna.tf32.f32 %0, %1;" : "=r"(r) : "f"(x));
    return r;
}
__device__ __forceinline__ uint32_t fu(float x) { return __float_as_uint(x); }

__device__ __forceinline__ void mma_tf32(float c[4],
    uint32_t a0, uint32_t a1, uint32_t a2, uint32_t a3,
    uint32_t b0, uint32_t b1)
{
    asm volatile(
        "mma.sync.aligned.m16n8k8.row.col.f32.tf32.tf32.f32 "
        "{%0,%1,%2,%3}, {%4,%5,%6,%7}, {%8,%9}, {%0,%1,%2,%3};\n"
        : "+f"(c[0]), "+f"(c[1]), "+f"(c[2]), "+f"(c[3])
        : "r"(a0), "r"(a1), "r"(a2), "r"(a3), "r"(b0), "r"(b1));
}

// ---------------------------------------------------------------------------
// C[m,n] = sum_k A[m,k]*W[n,k] + bias[n]   (NT, both K-contiguous row-major)
// CTA tile 128(M) x 64(N), 256 threads = 8 warps (4m x 2n), warp 32x32.
// tf32 m16n8k8 fragments. smem stride 36 -> fragment loads conflict-free.
// ---------------------------------------------------------------------------
__global__ __launch_bounds__(256) void gemm_nt_tc(GArgs args) {
    const int N = HID, K = HID;
    __shared__ uint32_t As[128*36];
    __shared__ uint32_t Bs[64*36];
    const int z = blockIdx.z;
    const float* __restrict__ A = args.A[z];
    const float* __restrict__ W = args.W[z];
    const float* __restrict__ bias = args.bias[z];
    float* __restrict__ C = args.C[z];

    const int tid = threadIdx.x;
    const int wid = tid >> 5, lane = tid & 31;
    const int g = lane >> 2, tig = lane & 3;
    const int wm = wid >> 1, wn = wid & 1;
    const int m0 = blockIdx.y * 128, n0 = blockIdx.x * 64;

    float c[2][4][4] = {};

    for (int k0 = 0; k0 < K; k0 += 32) {
        // load A tile: 128x32 = 1024 float4 / 256 threads = 4 each
        #pragma unroll
        for (int i = 0; i < 4; ++i) {
            int f = tid + i * 256;
            int r = f >> 3, c4 = f & 7;
            float4 v = *(const float4*)&A[(size_t)(m0 + r) * K + k0 + c4 * 4];
            uint4 u;
            u.x = cvt_tf32(v.x); u.y = cvt_tf32(v.y);
            u.z = cvt_tf32(v.z); u.w = cvt_tf32(v.w);
            *(uint4*)&As[r * 36 + c4 * 4] = u;
        }
        // load B tile: 64x32 = 512 float4 / 256 = 2 each
        #pragma unroll
        for (int i = 0; i < 2; ++i) {
            int f = tid + i * 256;
            int r = f >> 3, c4 = f & 7;
            float4 v = *(const float4*)&W[(size_t)(n0 + r) * K + k0 + c4 * 4];
            uint4 u;
            u.x = cvt_tf32(v.x); u.y = cvt_tf32(v.y);
            u.z = cvt_tf32(v.z); u.w = cvt_tf32(v.w);
            *(uint4*)&Bs[r * 36 + c4 * 4] = u;
        }
        __syncthreads();

        #pragma unroll
        for (int ks = 0; ks < 4; ++ks) {
            const int kc = ks * 8;
            uint32_t a[2][4];
            #pragma unroll
            for (int mt = 0; mt < 2; ++mt) {
                const int row = wm * 32 + mt * 16;
                a[mt][0] = As[(row + g    ) * 36 + kc + tig    ];
                a[mt][1] = As[(row + g + 8) * 36 + kc + tig    ];
                a[mt][2] = As[(row + g    ) * 36 + kc + tig + 4];
                a[mt][3] = As[(row + g + 8) * 36 + kc + tig + 4];
            }
            uint32_t b[4][2];
            #pragma unroll
            for (int nt = 0; nt < 4; ++nt) {
                const int col = wn * 32 + nt * 8;
                b[nt][0] = Bs[(col + g) * 36 + kc + tig    ];
                b[nt][1] = Bs[(col + g) * 36 + kc + tig + 4];
            }
            #pragma unroll
            for (int mt = 0; mt < 2; ++mt)
                #pragma unroll
                for (int nt = 0; nt < 4; ++nt)
                    mma_tf32(c[mt][nt], a[mt][0], a[mt][1], a[mt][2], a[mt][3],
                             b[nt][0], b[nt][1]);
        }
        __syncthreads();
    }

    #pragma unroll
    for (int mt = 0; mt < 2; ++mt) {
        const int row = m0 + wm * 32 + mt * 16 + g;
        #pragma unroll
        for (int nt = 0; nt < 4; ++nt) {
            const int col = n0 + wn * 32 + nt * 8 + 2 * tig;
            const float bx = bias[col], by = bias[col + 1];
            float2 v01 = make_float2(c[mt][nt][0] + bx, c[mt][nt][1] + by);
            float2 v23 = make_float2(c[mt][nt][2] + bx, c[mt][nt][3] + by);
            *(float2*)&C[(size_t)row * N + col] = v01;
            *(float2*)&C[(size_t)(row + 8) * N + col] = v23;
        }
    }
}

// ---------------------------------------------------------------------------
// Flash-style causal attention with relative-position terms, tf32 mma.
// CTA: 64 q-rows per (b,h); 128 threads = 4 warps; warp owns 16 q-rows.
// smem: Qs/Ps[64*68] (reused), Ks[64*68], Vst[64*64] (d-major, XOR swizzle),
//       prel[64*6], nearw[64*5]
// ---------------------------------------------------------------------------
__global__ __launch_bounds__(128) void attn_tc(
    const float* __restrict__ gq, const float* __restrict__ gk,
    const float* __restrict__ gv, const float* __restrict__ relk,
    const float* __restrict__ relv, float* __restrict__ gctx)
{
    extern __shared__ float sm[];
    float* Qs   = sm;                 // 64*68, reused as Ps after Q frags cached
    float* Ks   = Qs + 64 * 68;       // 64*68
    float* Vst  = Ks + 64 * 68;       // 64*64, Vst[d][key^swz]
    float* prel = Vst + 64 * 64;      // [64][6]
    float* nearw = prel + 64 * 6;     // [64][5]

    const int tid = threadIdx.x;
    const int wid = tid >> 5, lane = tid & 31;
    const int g = lane >> 2, tig = lane & 3;
    const int qt = blockIdx.x, h = blockIdx.y, b = blockIdx.z;
    const int q0 = qt * 64;
    const int rw = wid * 16;          // warp's first q-row (local)
    const size_t base = ((size_t)b * LL) * HID + (size_t)h * HD;

    // Load Q tile (tf32-rounded bit patterns)
    #pragma unroll
    for (int i = 0; i < 8; ++i) {
        int f = tid + i * 128;
        int r = f >> 4, c4 = f & 15;
        float4 v = *(const float4*)&gq[base + (size_t)(q0 + r) * HID + c4 * 4];
        uint4 u;
        u.x = cvt_tf32(v.x); u.y = cvt_tf32(v.y);
        u.z = cvt_tf32(v.z); u.w = cvt_tf32(v.w);
        *(uint4*)&Qs[r * 68 + c4 * 4] = u;
    }
    for (int idx = tid; idx < 64 * 5; idx += 128) nearw[idx] = 0.f;
    __syncthreads();

    // prel[r][j] = Q[r] . rel_k[j]   (Q is tf32-rounded; fine at 1e-3 budget)
    for (int idx = tid; idx < 64 * 6; idx += 128) {
        int r = idx / 6, j = idx % 6;
        float s = 0.f;
        #pragma unroll
        for (int d = 0; d < HD; ++d) s = fmaf(Qs[r * 68 + d], relk[j * HD + d], s);
        prel[r * 6 + j] = s;
    }

    // Cache Q A-fragments in registers (frees Qs smem for P)
    uint32_t qa[8][4];
    #pragma unroll
    for (int k8 = 0; k8 < 8; ++k8) {
        const int kc = k8 * 8;
        qa[k8][0] = fu(Qs[(rw + g    ) * 68 + kc + tig    ]);
        qa[k8][1] = fu(Qs[(rw + g + 8) * 68 + kc + tig    ]);
        qa[k8][2] = fu(Qs[(rw + g    ) * 68 + kc + tig + 4]);
        qa[k8][3] = fu(Qs[(rw + g + 8) * 68 + kc + tig + 4]);
    }

    float m0r = -1e30f, m1r = -1e30f, l0r = 0.f, l1r = 0.f;
    float o[8][4] = {};

    for (int kt = 0; kt <= qt; ++kt) {
        __syncthreads();   // Ks/Vst reuse; also orders prel reads before P writes
        // load K tile
        #pragma unroll
        for (int i = 0; i < 8; ++i) {
            int f = tid + i * 128;
            int r = f >> 4, c4 = f & 15;
            float4 v = *(const float4*)&gk[base + (size_t)(kt * 64 + r) * HID + c4 * 4];
            uint4 u;
            u.x = cvt_tf32(v.x); u.y = cvt_tf32(v.y);
            u.z = cvt_tf32(v.z); u.w = cvt_tf32(v.w);
            *(uint4*)&Ks[r * 68 + c4 * 4] = u;
        }
        // load V tile transposed into Vst[d][key] with XOR swizzle
        #pragma unroll
        for (int i = 0; i < 8; ++i) {
            int f = tid + i * 128;     // 1024 = 16 keyquads x 64 d
            int d = f & 63, kq = f >> 6;
            const float* vp = &gv[base + (size_t)(kt * 64 + kq * 4) * HID + d];
            uint4 u;
            u.x = cvt_tf32(vp[0]);
            u.y = cvt_tf32(vp[HID]);
            u.z = cvt_tf32(vp[2 * HID]);
            u.w = cvt_tf32(vp[3 * HID]);
            int addr = d * 64 + ((kq * 4) ^ ((d & 7) * 4));
            *(uint4*)&Vst[addr] = u;
        }
        __syncthreads();

        // S = Q @ K^T  (warp: 16 x 64)
        float s[8][4] = {};
        #pragma unroll
        for (int k8 = 0; k8 < 8; ++k8) {
            const int kc = k8 * 8;
            #pragma unroll
            for (int nt = 0; nt < 8; ++nt) {
                uint32_t b0 = fu(Ks[(nt * 8 + g) * 68 + kc + tig    ]);
                uint32_t b1 = fu(Ks[(nt * 8 + g) * 68 + kc + tig + 4]);
                mma_tf32(s[nt], qa[k8][0], qa[k8][1], qa[k8][2], qa[k8][3], b0, b1);
            }
        }

        const int dq = (qt - kt) * 64;
        const bool neardiag = (dq <= 64);
        const int rl0 = rw + g, rl1 = rw + g + 8;

        // bias + mask
        float rm0 = -1e30f, rm1 = -1e30f;
        #pragma unroll
        for (int nt = 0; nt < 8; ++nt) {
            #pragma unroll
            for (int e = 0; e < 4; ++e) {
                const int rl = (e < 2) ? rl0 : rl1;
                const int col = nt * 8 + 2 * tig + (e & 1);
                const int d = dq + rl - col;
                if (d < 0) s[nt][e] = -1e30f;
                else {
                    const int id = (d >= 5) ? 0 : (5 - d);
                    s[nt][e] = (s[nt][e] + prel[rl * 6 + id]) * 0.125f;
                }
            }
            rm0 = fmaxf(rm0, fmaxf(s[nt][0], s[nt][1]));
            rm1 = fmaxf(rm1, fmaxf(s[nt][2], s[nt][3]));
        }
        rm0 = fmaxf(rm0, __shfl_xor_sync(0xffffffffu, rm0, 1));
        rm0 = fmaxf(rm0, __shfl_xor_sync(0xffffffffu, rm0, 2));
        rm1 = fmaxf(rm1, __shfl_xor_sync(0xffffffffu, rm1, 1));
        rm1 = fmaxf(rm1, __shfl_xor_sync(0xffffffffu, rm1, 2));

        const float mn0 = fmaxf(m0r, rm0), mn1 = fmaxf(m1r, rm1);
        const float sc0 = __expf(m0r - mn0), sc1 = __expf(m1r - mn1);
        float ls0 = 0.f, ls1 = 0.f;
        #pragma unroll
        for (int nt = 0; nt < 8; ++nt) {
            s[nt][0] = __expf(s[nt][0] - mn0);
            s[nt][1] = __expf(s[nt][1] - mn0);
            s[nt][2] = __expf(s[nt][2] - mn1);
            s[nt][3] = __expf(s[nt][3] - mn1);
            ls0 += s[nt][0] + s[nt][1];
            ls1 += s[nt][2] + s[nt][3];
        }
        ls0 += __shfl_xor_sync(0xffffffffu, ls0, 1);
        ls0 += __shfl_xor_sync(0xffffffffu, ls0, 2);
        ls1 += __shfl_xor_sync(0xffffffffu, ls1, 1);
        ls1 += __shfl_xor_sync(0xffffffffu, ls1, 2);

        m0r = mn0; m1r = mn1;
        l0r = l0r * sc0 + ls0;
        l1r = l1r * sc1 + ls1;
        #pragma unroll
        for (int dt = 0; dt < 8; ++dt) {
            o[dt][0] *= sc0; o[dt][1] *= sc0;
            o[dt][2] *= sc1; o[dt][3] *= sc1;
        }

        if (neardiag) {
            if (tig == 0) {
                #pragma unroll
                for (int dd = 0; dd < 5; ++dd) {
                    nearw[rl0 * 5 + dd] *= sc0;
                    nearw[rl1 * 5 + dd] *= sc1;
                }
            }
            __syncwarp();
            #pragma unroll
            for (int nt = 0; nt < 8; ++nt) {
                #pragma unroll
                for (int e = 0; e < 4; ++e) {
                    const int rl = (e < 2) ? rl0 : rl1;
                    const int col = nt * 8 + 2 * tig + (e & 1);
                    const int d = dq + rl - col;
                    if (d >= 0 && d < 5) nearw[rl * 5 + d] = s[nt][e];
                }
            }
        }

        // write P into Qs (reused region), tf32-rounded patterns
        #pragma unroll
        for (int nt = 0; nt < 8; ++nt) {
            uint2 p01, p23;
            p01.x = cvt_tf32(s[nt][0]); p01.y = cvt_tf32(s[nt][1]);
            p23.x = cvt_tf32(s[nt][2]); p23.y = cvt_tf32(s[nt][3]);
            *(uint2*)&Qs[rl0 * 68 + nt * 8 + 2 * tig] = p01;
            *(uint2*)&Qs[rl1 * 68 + nt * 8 + 2 * tig] = p23;
        }
        __syncwarp();

        // O += P @ V
        #pragma unroll
        for (int k8 = 0; k8 < 8; ++k8) {
            const int kc = k8 * 8;
            uint32_t pa0 = fu(Qs[rl0 * 68 + kc + tig    ]);
            uint32_t pa1 = fu(Qs[rl1 * 68 + kc + tig    ]);
            uint32_t pa2 = fu(Qs[rl0 * 68 + kc + tig + 4]);
            uint32_t pa3 = fu(Qs[rl1 * 68 + kc + tig + 4]);
            #pragma unroll
            for (int dt = 0; dt < 8; ++dt) {
                const int dr = dt * 8 + g;
                uint32_t b0 = fu(Vst[dr * 64 + ((kc + tig    ) ^ (g * 4))]);
                uint32_t b1 = fu(Vst[dr * 64 + ((kc + tig + 4) ^ (g * 4))]);
                mma_tf32(o[dt], pa0, pa1, pa2, pa3, b0, b1);
            }
        }
    }
    __syncwarp();

    // Epilogue: rel_v near/far trick + normalize
    const int rl0 = rw + g, rl1 = rw + g + 8;
    const float inv0 = 1.f / l0r, inv1 = 1.f / l1r;
    const float a0 = nearw[rl0*5+0], a1 = nearw[rl0*5+1], a2 = nearw[rl0*5+2],
                a3 = nearw[rl0*5+3], a4 = nearw[rl0*5+4];
    const float b0 = nearw[rl1*5+0], b1 = nearw[rl1*5+1], b2 = nearw[rl1*5+2],
                b3 = nearw[rl1*5+3], b4 = nearw[rl1*5+4];
    const float far0 = l0r - (a0 + a1 + a2 + a3 + a4);
    const float far1 = l1r - (b0 + b1 + b2 + b3 + b4);

    #pragma unroll
    for (int dt = 0; dt < 8; ++dt) {
        const int c = dt * 8 + 2 * tig;
        #pragma unroll
        for (int j = 0; j < 2; ++j) {
            const int cc = c + j;
            const float r5 = relv[5*HD+cc], r4 = relv[4*HD+cc], r3 = relv[3*HD+cc],
                        r2 = relv[2*HD+cc], r1 = relv[1*HD+cc], r0 = relv[cc];
            float e0 = a0*r5 + a1*r4 + a2*r3 + a3*r2 + a4*r1 + far0*r0;
            float e1 = b0*r5 + b1*r4 + b2*r3 + b3*r2 + b4*r1 + far1*r0;
            gctx[base + (size_t)(q0 + rl0) * HID + cc] = (o[dt][j]     + e0) * inv0;
            gctx[base + (size_t)(q0 + rl1) * HID + cc] = (o[dt][2 + j] + e1) * inv1;
        }
    }
}

extern "C" void kernel_launch(void* const* d_in, const int* in_sizes, int n_in,
                              void* d_out, int out_size) {
    (void)in_sizes; (void)n_in; (void)out_size;
    const float* query = (const float*)d_in[0];
    const float* key   = (const float*)d_in[1];
    const float* value = (const float*)d_in[2];
    const float* Wq = (const float*)d_in[3];
    const float* bq = (const float*)d_in[4];
    const float* Wk = (const float*)d_in[5];
    const float* bk = (const float*)d_in[6];
    const float* Wv = (const float*)d_in[7];
    const float* bv = (const float*)d_in[8];
    const float* Wo = (const float*)d_in[9];
    const float* bo = (const float*)d_in[10];
    const float* relk = (const float*)d_in[11];
    const float* relv = (const float*)d_in[12];

    float *pq, *pk, *pv, *pctx;
    cudaGetSymbolAddress((void**)&pq,  g_q);
    cudaGetSymbolAddress((void**)&pk,  g_k);
    cudaGetSymbolAddress((void**)&pv,  g_v);
    cudaGetSymbolAddress((void**)&pctx, g_ctx);

    // 1) QKV projections (one launch, grid.z = 3)
    GArgs qkv;
    qkv.A[0] = query; qkv.W[0] = Wq; qkv.bias[0] = bq; qkv.C[0] = pq;
    qkv.A[1] = key;   qkv.W[1] = Wk; qkv.bias[1] = bk; qkv.C[1] = pk;
    qkv.A[2] = value; qkv.W[2] = Wv; qkv.bias[2] = bv; qkv.C[2] = pv;
    gemm_nt_tc<<<dim3(HID/64, (BB*LL)/128, 3), 256>>>(qkv);

    // 2) attention
    const int SMEM = (64*68*2 + 64*64 + 64*6 + 64*5) * (int)sizeof(float);
    cudaFuncSetAttribute(attn_tc,
                         cudaFuncAttributeMaxDynamicSharedMemorySize, SMEM);
    attn_tc<<<dim3(LL/64, HEADS, BB), 128, SMEM>>>(pq, pk, pv, relk, relv, pctx);

    // 3) output projection
    GArgs og;
    og.A[0] = pctx; og.W[0] = Wo; og.bias[0] = bo; og.C[0] = (float*)d_out;
    og.A[1] = og.A[0]; og.W[1] = og.W[0]; og.bias[1] = og.bias[0]; og.C[1] = og.C[0];
    og.A[2] = og.A[0]; og.W[2] = og.W[0]; og.bias[2] = og.bias[0]; og.C[2] = og.C[0];
    gemm_nt_tc<<<dim3(HID/64, (BB*LL)/128, 1), 256>>>(og);
}

// round 5
// speedup vs baseline: 3.1114x; 1.1288x over previous
#include <cuda_runtime.h>
#include <math.h>
#include <stdint.h>

#define BB 4
#define LL 1024
#define HID 512
#define HEADS 8
#define HD 64

// Scratch (device globals: allocation-free)
__device__ float g_q[BB*LL*HID];
__device__ float g_k[BB*LL*HID];
__device__ float g_v[BB*LL*HID];
__device__ float g_ctx[BB*LL*HID];

struct GArgs {
    const float* A[3];
    const float* W[3];
    const float* bias[3];
    float* C[3];
};

// tf32 round (rna) -> 32-bit pattern in a b32 register
__device__ __forceinline__ uint32_t cvt_tf32(float x) {
    uint32_t r;
    asm("cvt.rna.tf32.f32 %0, %1;" : "=r"(r) : "f"(x));
    return r;
}
__device__ __forceinline__ uint32_t fu(float x) { return __float_as_uint(x); }
__device__ __forceinline__ uint4 cvt4(float4 v) {
    uint4 u;
    u.x = cvt_tf32(v.x); u.y = cvt_tf32(v.y);
    u.z = cvt_tf32(v.z); u.w = cvt_tf32(v.w);
    return u;
}

__device__ __forceinline__ void mma_tf32(float c[4],
    uint32_t a0, uint32_t a1, uint32_t a2, uint32_t a3,
    uint32_t b0, uint32_t b1)
{
    asm volatile(
        "mma.sync.aligned.m16n8k8.row.col.f32.tf32.tf32.f32 "
        "{%0,%1,%2,%3}, {%4,%5,%6,%7}, {%8,%9}, {%0,%1,%2,%3};\n"
        : "+f"(c[0]), "+f"(c[1]), "+f"(c[2]), "+f"(c[3])
        : "r"(a0), "r"(a1), "r"(a2), "r"(a3), "r"(b0), "r"(b1));
}

// ---------------------------------------------------------------------------
// C[m,n] = sum_k A[m,k]*W[n,k] + bias[n]   (NT, both K-contiguous row-major)
// CTA tile 128(M) x 64(N), 256 threads = 8 warps (4m x 2n), warp 32x32.
// Register-staged double-buffered smem pipeline; 1 barrier per k-tile.
// ---------------------------------------------------------------------------
#define AS_STRIDE 4608   // 128*36
#define BS_STRIDE 2304   // 64*36
__global__ __launch_bounds__(256) void gemm_nt_tc(GArgs args) {
    const int N = HID, K = HID;
    extern __shared__ uint32_t smg[];
    uint32_t* As = smg;                    // [2][128*36]
    uint32_t* Bs = smg + 2 * AS_STRIDE;    // [2][64*36]

    const int z = blockIdx.z;
    const float* __restrict__ A = args.A[z];
    const float* __restrict__ W = args.W[z];
    const float* __restrict__ bias = args.bias[z];
    float* __restrict__ C = args.C[z];

    const int tid = threadIdx.x;
    const int wid = tid >> 5, lane = tid & 31;
    const int g = lane >> 2, tig = lane & 3;
    const int wm = wid >> 1, wn = wid & 1;
    const int m0 = blockIdx.y * 128, n0 = blockIdx.x * 64;

    const int fa_r = tid >> 3, fa_c = (tid & 7) * 4;  // A/B load coords

    float c[2][4][4] = {};
    float4 ra[4], rb[2];

    // prologue: tile 0 -> regs -> smem[0]
    #pragma unroll
    for (int i = 0; i < 4; ++i)
        ra[i] = *(const float4*)&A[(size_t)(m0 + fa_r + i * 32) * K + fa_c];
    #pragma unroll
    for (int i = 0; i < 2; ++i)
        rb[i] = *(const float4*)&W[(size_t)(n0 + fa_r + i * 32) * K + fa_c];
    #pragma unroll
    for (int i = 0; i < 4; ++i)
        *(uint4*)&As[(fa_r + i * 32) * 36 + fa_c] = cvt4(ra[i]);
    #pragma unroll
    for (int i = 0; i < 2; ++i)
        *(uint4*)&Bs[(fa_r + i * 32) * 36 + fa_c] = cvt4(rb[i]);
    __syncthreads();

    #pragma unroll 2
    for (int k0 = 0; k0 < K; k0 += 32) {
        const int buf = (k0 >> 5) & 1;
        const uint32_t* Ac = As + buf * AS_STRIDE;
        const uint32_t* Bc = Bs + buf * BS_STRIDE;
        const bool has_next = (k0 + 32) < K;

        // issue next tile's LDGs (latency hides under the MMAs below)
        if (has_next) {
            const int k1 = k0 + 32;
            #pragma unroll
            for (int i = 0; i < 4; ++i)
                ra[i] = *(const float4*)&A[(size_t)(m0 + fa_r + i * 32) * K + k1 + fa_c];
            #pragma unroll
            for (int i = 0; i < 2; ++i)
                rb[i] = *(const float4*)&W[(size_t)(n0 + fa_r + i * 32) * K + k1 + fa_c];
        }

        // compute current tile
        #pragma unroll
        for (int ks = 0; ks < 4; ++ks) {
            const int kc = ks * 8;
            uint32_t a[2][4];
            #pragma unroll
            for (int mt = 0; mt < 2; ++mt) {
                const int row = wm * 32 + mt * 16;
                a[mt][0] = Ac[(row + g    ) * 36 + kc + tig    ];
                a[mt][1] = Ac[(row + g + 8) * 36 + kc + tig    ];
                a[mt][2] = Ac[(row + g    ) * 36 + kc + tig + 4];
                a[mt][3] = Ac[(row + g + 8) * 36 + kc + tig + 4];
            }
            uint32_t b[4][2];
            #pragma unroll
            for (int nt = 0; nt < 4; ++nt) {
                const int col = wn * 32 + nt * 8;
                b[nt][0] = Bc[(col + g) * 36 + kc + tig    ];
                b[nt][1] = Bc[(col + g) * 36 + kc + tig + 4];
            }
            #pragma unroll
            for (int mt = 0; mt < 2; ++mt)
                #pragma unroll
                for (int nt = 0; nt < 4; ++nt)
                    mma_tf32(c[mt][nt], a[mt][0], a[mt][1], a[mt][2], a[mt][3],
                             b[nt][0], b[nt][1]);
        }

        // stage next tile into the other buffer
        if (has_next) {
            uint32_t* An = As + (buf ^ 1) * AS_STRIDE;
            uint32_t* Bn = Bs + (buf ^ 1) * BS_STRIDE;
            #pragma unroll
            for (int i = 0; i < 4; ++i)
                *(uint4*)&An[(fa_r + i * 32) * 36 + fa_c] = cvt4(ra[i]);
            #pragma unroll
            for (int i = 0; i < 2; ++i)
                *(uint4*)&Bn[(fa_r + i * 32) * 36 + fa_c] = cvt4(rb[i]);
        }
        __syncthreads();
    }

    #pragma unroll
    for (int mt = 0; mt < 2; ++mt) {
        const int row = m0 + wm * 32 + mt * 16 + g;
        #pragma unroll
        for (int nt = 0; nt < 4; ++nt) {
            const int col = n0 + wn * 32 + nt * 8 + 2 * tig;
            const float bx = bias[col], by = bias[col + 1];
            float2 v01 = make_float2(c[mt][nt][0] + bx, c[mt][nt][1] + by);
            float2 v23 = make_float2(c[mt][nt][2] + bx, c[mt][nt][3] + by);
            *(float2*)&C[(size_t)row * N + col] = v01;
            *(float2*)&C[(size_t)(row + 8) * N + col] = v23;
        }
    }
}

// ---------------------------------------------------------------------------
// Flash-style causal attention with relative-position terms, tf32 mma.
// CTA: 64 q-rows per (b,h); 128 threads = 4 warps; warp owns 16 q-rows.
// K/V tiles prefetched into registers one iteration ahead.
// ---------------------------------------------------------------------------
__global__ __launch_bounds__(128) void attn_tc(
    const float* __restrict__ gq, const float* __restrict__ gk,
    const float* __restrict__ gv, const float* __restrict__ relk,
    const float* __restrict__ relv, float* __restrict__ gctx)
{
    extern __shared__ float sm[];
    float* Qs   = sm;                 // 64*68, reused as Ps after Q frags cached
    float* Ks   = Qs + 64 * 68;       // 64*68
    float* Vst  = Ks + 64 * 68;       // 64*64, Vst[d][key^swz]
    float* prel = Vst + 64 * 64;      // [64][6]
    float* nearw = prel + 64 * 6;     // [64][5]

    const int tid = threadIdx.x;
    const int wid = tid >> 5, lane = tid & 31;
    const int g = lane >> 2, tig = lane & 3;
    const int qt = blockIdx.x, h = blockIdx.y, b = blockIdx.z;
    const int q0 = qt * 64;
    const int rw = wid * 16;          // warp's first q-row (local)
    const size_t base = ((size_t)b * LL) * HID + (size_t)h * HD;

    const int fr = tid >> 4, fc = (tid & 15) * 4;   // K-tile load coords
    const int vd = tid & 63;                        // V-tile gather: d coord

    // Load Q tile (tf32-rounded bit patterns)
    #pragma unroll
    for (int i = 0; i < 8; ++i) {
        int r = fr + i * 8;
        float4 v = *(const float4*)&gq[base + (size_t)(q0 + r) * HID + fc];
        *(uint4*)&Qs[r * 68 + fc] = cvt4(v);
    }
    for (int idx = tid; idx < 64 * 5; idx += 128) nearw[idx] = 0.f;
    __syncthreads();

    // prel[r][j] = Q[r] . rel_k[j]
    for (int idx = tid; idx < 64 * 6; idx += 128) {
        int r = idx / 6, j = idx % 6;
        float s = 0.f;
        #pragma unroll
        for (int d = 0; d < HD; ++d) s = fmaf(Qs[r * 68 + d], relk[j * HD + d], s);
        prel[r * 6 + j] = s;
    }

    // Cache Q A-fragments in registers (frees Qs smem for P)
    uint32_t qa[8][4];
    #pragma unroll
    for (int k8 = 0; k8 < 8; ++k8) {
        const int kc = k8 * 8;
        qa[k8][0] = fu(Qs[(rw + g    ) * 68 + kc + tig    ]);
        qa[k8][1] = fu(Qs[(rw + g + 8) * 68 + kc + tig    ]);
        qa[k8][2] = fu(Qs[(rw + g    ) * 68 + kc + tig + 4]);
        qa[k8][3] = fu(Qs[(rw + g + 8) * 68 + kc + tig + 4]);
    }

    // prologue: prefetch K/V tile 0 into registers
    // K: thread loads rows fr+8i, cols [fc,fc+4)
    // V: thread gathers key-quad kq=(tid>>6)+2i at depth vd (transposed)
    float4 rk[8], rv[8];
    #pragma unroll
    for (int i = 0; i < 8; ++i)
        rk[i] = *(const float4*)&gk[base + (size_t)(fr + i * 8) * HID + fc];
    #pragma unroll
    for (int i = 0; i < 8; ++i) {
        const int kq = (tid >> 6) + i * 2;
        const float* vp = &gv[base + (size_t)(kq * 4) * HID + vd];
        rv[i] = make_float4(vp[0], vp[HID], vp[2 * HID], vp[3 * HID]);
    }

    float m0r = -1e30f, m1r = -1e30f, l0r = 0.f, l1r = 0.f;
    float o[8][4] = {};

    for (int kt = 0; kt <= qt; ++kt) {
        __syncthreads();   // previous iteration's smem readers done
        // store prefetched K tile
        #pragma unroll
        for (int i = 0; i < 8; ++i)
            *(uint4*)&Ks[(fr + i * 8) * 68 + fc] = cvt4(rk[i]);
        // store prefetched V tile transposed with XOR swizzle
        #pragma unroll
        for (int i = 0; i < 8; ++i) {
            const int kq = (tid >> 6) + i * 2;
            int addr = vd * 64 + ((kq * 4) ^ ((vd & 7) * 4));
            *(uint4*)&Vst[addr] = cvt4(rv[i]);
        }
        __syncthreads();

        // prefetch next K/V tile (hides under compute below)
        if (kt < qt) {
            const int kn = (kt + 1) * 64;
            #pragma unroll
            for (int i = 0; i < 8; ++i)
                rk[i] = *(const float4*)&gk[base + (size_t)(kn + fr + i * 8) * HID + fc];
            #pragma unroll
            for (int i = 0; i < 8; ++i) {
                const int kq = (tid >> 6) + i * 2;
                const float* vp = &gv[base + (size_t)(kn + kq * 4) * HID + vd];
                rv[i] = make_float4(vp[0], vp[HID], vp[2 * HID], vp[3 * HID]);
            }
        }

        // S = Q @ K^T  (warp: 16 x 64)
        float s[8][4] = {};
        #pragma unroll
        for (int k8 = 0; k8 < 8; ++k8) {
            const int kc = k8 * 8;
            #pragma unroll
            for (int nt = 0; nt < 8; ++nt) {
                uint32_t b0 = fu(Ks[(nt * 8 + g) * 68 + kc + tig    ]);
                uint32_t b1 = fu(Ks[(nt * 8 + g) * 68 + kc + tig + 4]);
                mma_tf32(s[nt], qa[k8][0], qa[k8][1], qa[k8][2], qa[k8][3], b0, b1);
            }
        }

        const int dq = (qt - kt) * 64;
        const bool neardiag = (dq <= 64);
        const int rl0 = rw + g, rl1 = rw + g + 8;

        // bias + mask
        float rm0 = -1e30f, rm1 = -1e30f;
        #pragma unroll
        for (int nt = 0; nt < 8; ++nt) {
            #pragma unroll
            for (int e = 0; e < 4; ++e) {
                const int rl = (e < 2) ? rl0 : rl1;
                const int col = nt * 8 + 2 * tig + (e & 1);
                const int d = dq + rl - col;
                if (d < 0) s[nt][e] = -1e30f;
                else {
                    const int id = (d >= 5) ? 0 : (5 - d);
                    s[nt][e] = (s[nt][e] + prel[rl * 6 + id]) * 0.125f;
                }
            }
            rm0 = fmaxf(rm0, fmaxf(s[nt][0], s[nt][1]));
            rm1 = fmaxf(rm1, fmaxf(s[nt][2], s[nt][3]));
        }
        rm0 = fmaxf(rm0, __shfl_xor_sync(0xffffffffu, rm0, 1));
        rm0 = fmaxf(rm0, __shfl_xor_sync(0xffffffffu, rm0, 2));
        rm1 = fmaxf(rm1, __shfl_xor_sync(0xffffffffu, rm1, 1));
        rm1 = fmaxf(rm1, __shfl_xor_sync(0xffffffffu, rm1, 2));

        const float mn0 = fmaxf(m0r, rm0), mn1 = fmaxf(m1r, rm1);
        const float sc0 = __expf(m0r - mn0), sc1 = __expf(m1r - mn1);
        float ls0 = 0.f, ls1 = 0.f;
        #pragma unroll
        for (int nt = 0; nt < 8; ++nt) {
            s[nt][0] = __expf(s[nt][0] - mn0);
            s[nt][1] = __expf(s[nt][1] - mn0);
            s[nt][2] = __expf(s[nt][2] - mn1);
            s[nt][3] = __expf(s[nt][3] - mn1);
            ls0 += s[nt][0] + s[nt][1];
            ls1 += s[nt][2] + s[nt][3];
        }
        ls0 += __shfl_xor_sync(0xffffffffu, ls0, 1);
        ls0 += __shfl_xor_sync(0xffffffffu, ls0, 2);
        ls1 += __shfl_xor_sync(0xffffffffu, ls1, 1);
        ls1 += __shfl_xor_sync(0xffffffffu, ls1, 2);

        m0r = mn0; m1r = mn1;
        l0r = l0r * sc0 + ls0;
        l1r = l1r * sc1 + ls1;
        #pragma unroll
        for (int dt = 0; dt < 8; ++dt) {
            o[dt][0] *= sc0; o[dt][1] *= sc0;
            o[dt][2] *= sc1; o[dt][3] *= sc1;
        }

        if (neardiag) {
            if (tig == 0) {
                #pragma unroll
                for (int dd = 0; dd < 5; ++dd) {
                    nearw[rl0 * 5 + dd] *= sc0;
                    nearw[rl1 * 5 + dd] *= sc1;
                }
            }
            __syncwarp();
            #pragma unroll
            for (int nt = 0; nt < 8; ++nt) {
                #pragma unroll
                for (int e = 0; e < 4; ++e) {
                    const int rl = (e < 2) ? rl0 : rl1;
                    const int col = nt * 8 + 2 * tig + (e & 1);
                    const int d = dq + rl - col;
                    if (d >= 0 && d < 5) nearw[rl * 5 + d] = s[nt][e];
                }
            }
        }

        // write P into Qs (reused region), tf32-rounded patterns
        #pragma unroll
        for (int nt = 0; nt < 8; ++nt) {
            uint2 p01, p23;
            p01.x = cvt_tf32(s[nt][0]); p01.y = cvt_tf32(s[nt][1]);
            p23.x = cvt_tf32(s[nt][2]); p23.y = cvt_tf32(s[nt][3]);
            *(uint2*)&Qs[rl0 * 68 + nt * 8 + 2 * tig] = p01;
            *(uint2*)&Qs[rl1 * 68 + nt * 8 + 2 * tig] = p23;
        }
        __syncwarp();

        // O += P @ V
        #pragma unroll
        for (int k8 = 0; k8 < 8; ++k8) {
            const int kc = k8 * 8;
            uint32_t pa0 = fu(Qs[rl0 * 68 + kc + tig    ]);
            uint32_t pa1 = fu(Qs[rl1 * 68 + kc + tig    ]);
            uint32_t pa2 = fu(Qs[rl0 * 68 + kc + tig + 4]);
            uint32_t pa3 = fu(Qs[rl1 * 68 + kc + tig + 4]);
            #pragma unroll
            for (int dt = 0; dt < 8; ++dt) {
                const int dr = dt * 8 + g;
                uint32_t b0 = fu(Vst[dr * 64 + ((kc + tig    ) ^ (g * 4))]);
                uint32_t b1 = fu(Vst[dr * 64 + ((kc + tig + 4) ^ (g * 4))]);
                mma_tf32(o[dt], pa0, pa1, pa2, pa3, b0, b1);
            }
        }
    }
    __syncwarp();

    // Epilogue: rel_v near/far trick + normalize
    const int rl0 = rw + g, rl1 = rw + g + 8;
    const float inv0 = 1.f / l0r, inv1 = 1.f / l1r;
    const float a0 = nearw[rl0*5+0], a1 = nearw[rl0*5+1], a2 = nearw[rl0*5+2],
                a3 = nearw[rl0*5+3], a4 = nearw[rl0*5+4];
    const float b0 = nearw[rl1*5+0], b1 = nearw[rl1*5+1], b2 = nearw[rl1*5+2],
                b3 = nearw[rl1*5+3], b4 = nearw[rl1*5+4];
    const float far0 = l0r - (a0 + a1 + a2 + a3 + a4);
    const float far1 = l1r - (b0 + b1 + b2 + b3 + b4);

    #pragma unroll
    for (int dt = 0; dt < 8; ++dt) {
        const int c = dt * 8 + 2 * tig;
        #pragma unroll
        for (int j = 0; j < 2; ++j) {
            const int cc = c + j;
            const float r5 = relv[5*HD+cc], r4 = relv[4*HD+cc], r3 = relv[3*HD+cc],
                        r2 = relv[2*HD+cc], r1 = relv[1*HD+cc], r0 = relv[cc];
            float e0 = a0*r5 + a1*r4 + a2*r3 + a3*r2 + a4*r1 + far0*r0;
            float e1 = b0*r5 + b1*r4 + b2*r3 + b3*r2 + b4*r1 + far1*r0;
            gctx[base + (size_t)(q0 + rl0) * HID + cc] = (o[dt][j]     + e0) * inv0;
            gctx[base + (size_t)(q0 + rl1) * HID + cc] = (o[dt][2 + j] + e1) * inv1;
        }
    }
}

extern "C" void kernel_launch(void* const* d_in, const int* in_sizes, int n_in,
                              void* d_out, int out_size) {
    (void)in_sizes; (void)n_in; (void)out_size;
    const float* query = (const float*)d_in[0];
    const float* key   = (const float*)d_in[1];
    const float* value = (const float*)d_in[2];
    const float* Wq = (const float*)d_in[3];
    const float* bq = (const float*)d_in[4];
    const float* Wk = (const float*)d_in[5];
    const float* bk = (const float*)d_in[6];
    const float* Wv = (const float*)d_in[7];
    const float* bv = (const float*)d_in[8];
    const float* Wo = (const float*)d_in[9];
    const float* bo = (const float*)d_in[10];
    const float* relk = (const float*)d_in[11];
    const float* relv = (const float*)d_in[12];

    float *pq, *pk, *pv, *pctx;
    cudaGetSymbolAddress((void**)&pq,  g_q);
    cudaGetSymbolAddress((void**)&pk,  g_k);
    cudaGetSymbolAddress((void**)&pv,  g_v);
    cudaGetSymbolAddress((void**)&pctx, g_ctx);

    const int GSMEM = 2 * (AS_STRIDE + BS_STRIDE) * (int)sizeof(uint32_t); // 55296
    cudaFuncSetAttribute(gemm_nt_tc,
                         cudaFuncAttributeMaxDynamicSharedMemorySize, GSMEM);

    // 1) QKV projections (one launch, grid.z = 3)
    GArgs qkv;
    qkv.A[0] = query; qkv.W[0] = Wq; qkv.bias[0] = bq; qkv.C[0] = pq;
    qkv.A[1] = key;   qkv.W[1] = Wk; qkv.bias[1] = bk; qkv.C[1] = pk;
    qkv.A[2] = value; qkv.W[2] = Wv; qkv.bias[2] = bv; qkv.C[2] = pv;
    gemm_nt_tc<<<dim3(HID/64, (BB*LL)/128, 3), 256, GSMEM>>>(qkv);

    // 2) attention
    const int SMEM = (64*68*2 + 64*64 + 64*6 + 64*5) * (int)sizeof(float);
    cudaFuncSetAttribute(attn_tc,
                         cudaFuncAttributeMaxDynamicSharedMemorySize, SMEM);
    attn_tc<<<dim3(LL/64, HEADS, BB), 128, SMEM>>>(pq, pk, pv, relk, relv, pctx);

    // 3) output projection
    GArgs og;
    og.A[0] = pctx; og.W[0] = Wo; og.bias[0] = bo; og.C[0] = (float*)d_out;
    og.A[1] = og.A[0]; og.W[1] = og.W[0]; og.bias[1] = og.bias[0]; og.C[1] = og.C[0];
    og.A[2] = og.A[0]; og.W[2] = og.W[0]; og.bias[2] = og.bias[0]; og.C[2] = og.C[0];
    gemm_nt_tc<<<dim3(HID/64, (BB*LL)/128, 1), 256, GSMEM>>>(og);
}